// round 3
// baseline (speedup 1.0000x reference)
#include <cuda_runtime.h>
#include <cuda_bf16.h>
#include <math.h>
#include <stdint.h>

#define BATCH 2
#define S_LEN 2048
#define D_MODEL 1024
#define NHEAD 16
#define DHEAD 64
#define NEGBIG -1e30f

// Scratch (allocation-free rule: __device__ globals)
__device__ float g_q[BATCH*NHEAD*S_LEN*DHEAD];
__device__ float g_k[BATCH*NHEAD*S_LEN*DHEAD];
__device__ float g_v[BATCH*NHEAD*S_LEN*DHEAD];
__device__ float g_att[BATCH*S_LEN*D_MODEL];

// ---------------------------------------------------------------------------
// 3xBF16 GEMM: C = A(MxK) @ B(KxN), K=1024. hi/lo bf16 split done ONCE at
// smem-fill time (hi/lo planes). BM=BN=128, BK=32, 256 threads, 8 warps in
// 4x2 grid of 32x64 warp tiles. mma.m16n8k16.bf16, fp32 accum.
// A smem: k-major, pitch 40 bf16. B smem: n-major (transposed at store),
// pitch 40 bf16. Both fragment loads are single 32-bit LDS, conflict-free.
// ---------------------------------------------------------------------------
#define BKG 32
#define GP 40                      // smem pitch in bf16
#define PLANE (128*GP)             // one plane (one buffer)

__device__ __forceinline__ void bf16split(float x, __nv_bfloat16& hi, __nv_bfloat16& lo) {
    hi = __float2bfloat16_rn(x);
    lo = __float2bfloat16_rn(x - __bfloat162float(hi));
}

__device__ __forceinline__ void mma_bf16(float* c, const uint32_t* a, const uint32_t* b) {
    asm volatile(
        "mma.sync.aligned.m16n8k16.row.col.f32.bf16.bf16.f32 "
        "{%0,%1,%2,%3}, {%4,%5,%6,%7}, {%8,%9}, {%0,%1,%2,%3};"
        : "+f"(c[0]), "+f"(c[1]), "+f"(c[2]), "+f"(c[3])
        : "r"(a[0]), "r"(a[1]), "r"(a[2]), "r"(a[3]), "r"(b[0]), "r"(b[1]));
}

template<int N, bool IS_QKV>
__global__ __launch_bounds__(256)
void bf16_gemm_kernel(const float* __restrict__ Ain,
                      const float* __restrict__ Bw,
                      float* __restrict__ Out)
{
    extern __shared__ __nv_bfloat16 smg[];
    __nv_bfloat16* Ah = smg;                 // [2][128*GP]
    __nv_bfloat16* Al = Ah + 2*PLANE;
    __nv_bfloat16* Bh = Al + 2*PLANE;        // n-major
    __nv_bfloat16* Bl = Bh + 2*PLANE;

    const int K = 1024;
    const float* A = IS_QKV ? Ain : (const float*)g_att;

    const int tid  = threadIdx.x;
    const int lane = tid & 31;
    const int wid  = tid >> 5;
    const int wm   = wid & 3;      // 32-row slab
    const int wn   = wid >> 2;     // 64-col slab
    const int m0 = blockIdx.y * 128;
    const int n0 = blockIdx.x * 128;

    // loader indices
    const int arow = tid >> 1;             // 128 rows, 2 thr/row
    const int akof = (tid & 1) * 16;       // 16 consecutive k per thread
    const int bkr  = tid >> 3;             // 32 k-rows, 8 thr/row
    const int bnof = (tid & 7) * 16;       // 16 consecutive n per thread

    float acc[2][8][4];
    #pragma unroll
    for (int mt = 0; mt < 2; mt++)
        #pragma unroll
        for (int nt = 0; nt < 8; nt++)
            #pragma unroll
            for (int i = 0; i < 4; i++) acc[mt][nt][i] = 0.f;

    float4 pa[4], pb[4];
    auto preload = [&](int k0) {
        const float* ap = A + (long)(m0 + arow)*K + k0 + akof;
        #pragma unroll
        for (int q = 0; q < 4; q++) pa[q] = *reinterpret_cast<const float4*>(ap + q*4);
        const float* bp = Bw + (long)(k0 + bkr)*N + n0 + bnof;
        #pragma unroll
        for (int q = 0; q < 4; q++) pb[q] = *reinterpret_cast<const float4*>(bp + q*4);
    };
    auto cvt_store = [&](int buf) {
        __nv_bfloat16* ah = Ah + buf*PLANE;
        __nv_bfloat16* al = Al + buf*PLANE;
        #pragma unroll
        for (int q = 0; q < 4; q++) {
            float f[4] = {pa[q].x, pa[q].y, pa[q].z, pa[q].w};
            #pragma unroll
            for (int p = 0; p < 2; p++) {
                __nv_bfloat16 h0,l0,h1,l1;
                bf16split(f[p*2+0], h0, l0);
                bf16split(f[p*2+1], h1, l1);
                int k = akof + q*4 + p*2;
                *reinterpret_cast<__nv_bfloat162*>(&ah[arow*GP + k]) = __nv_bfloat162(h0, h1);
                *reinterpret_cast<__nv_bfloat162*>(&al[arow*GP + k]) = __nv_bfloat162(l0, l1);
            }
        }
        __nv_bfloat16* bh = Bh + buf*PLANE;
        __nv_bfloat16* bl = Bl + buf*PLANE;
        #pragma unroll
        for (int q = 0; q < 4; q++) {
            float f[4] = {pb[q].x, pb[q].y, pb[q].z, pb[q].w};
            #pragma unroll
            for (int j = 0; j < 4; j++) {
                __nv_bfloat16 h, l;
                bf16split(f[j], h, l);
                int n = bnof + q*4 + j;
                bh[n*GP + bkr] = h;      // transposed (n-major)
                bl[n*GP + bkr] = l;
            }
        }
    };

    preload(0);

    const int NIT = K / BKG;
    for (int it = 0; it < NIT; ++it) {
        const int buf = it & 1;
        cvt_store(buf);
        if (it + 1 < NIT) preload((it+1)*BKG);
        __syncthreads();

        const __nv_bfloat16* ah_ = Ah + buf*PLANE;
        const __nv_bfloat16* al_ = Al + buf*PLANE;
        const __nv_bfloat16* bh_ = Bh + buf*PLANE;
        const __nv_bfloat16* bl_ = Bl + buf*PLANE;

        #pragma unroll
        for (int ks = 0; ks < 2; ks++) {
            const int kb = ks * 16 + (lane & 3) * 2;
            uint32_t ahf[2][4], alf[2][4];
            #pragma unroll
            for (int mt = 0; mt < 2; mt++) {
                int r = wm*32 + mt*16 + (lane >> 2);
                ahf[mt][0] = *reinterpret_cast<const uint32_t*>(&ah_[r*GP + kb]);
                ahf[mt][1] = *reinterpret_cast<const uint32_t*>(&ah_[(r+8)*GP + kb]);
                ahf[mt][2] = *reinterpret_cast<const uint32_t*>(&ah_[r*GP + kb + 8]);
                ahf[mt][3] = *reinterpret_cast<const uint32_t*>(&ah_[(r+8)*GP + kb + 8]);
                alf[mt][0] = *reinterpret_cast<const uint32_t*>(&al_[r*GP + kb]);
                alf[mt][1] = *reinterpret_cast<const uint32_t*>(&al_[(r+8)*GP + kb]);
                alf[mt][2] = *reinterpret_cast<const uint32_t*>(&al_[r*GP + kb + 8]);
                alf[mt][3] = *reinterpret_cast<const uint32_t*>(&al_[(r+8)*GP + kb + 8]);
            }
            uint32_t bhf[8][2], blf[8][2];
            #pragma unroll
            for (int nt = 0; nt < 8; nt++) {
                int c = wn*64 + nt*8 + (lane >> 2);
                bhf[nt][0] = *reinterpret_cast<const uint32_t*>(&bh_[c*GP + kb]);
                bhf[nt][1] = *reinterpret_cast<const uint32_t*>(&bh_[c*GP + kb + 8]);
                blf[nt][0] = *reinterpret_cast<const uint32_t*>(&bl_[c*GP + kb]);
                blf[nt][1] = *reinterpret_cast<const uint32_t*>(&bl_[c*GP + kb + 8]);
            }
            #pragma unroll
            for (int mt = 0; mt < 2; mt++)
                #pragma unroll
                for (int nt = 0; nt < 8; nt++) {
                    mma_bf16(acc[mt][nt], ahf[mt], blf[nt]);  // hi*lo
                    mma_bf16(acc[mt][nt], alf[mt], bhf[nt]);  // lo*hi
                    mma_bf16(acc[mt][nt], ahf[mt], bhf[nt]);  // hi*hi
                }
        }
        __syncthreads();
    }

    // ---- epilogue ----
    #pragma unroll
    for (int mt = 0; mt < 2; mt++) {
        #pragma unroll
        for (int i = 0; i < 2; i++) {
            int row = m0 + wm*32 + mt*16 + (lane >> 2) + i*8;
            #pragma unroll
            for (int nt = 0; nt < 8; nt++) {
                int col = n0 + wn*64 + nt*8 + (lane & 3)*2;
                float2 v = make_float2(acc[mt][nt][i*2+0], acc[mt][nt][i*2+1]);
                if (IS_QKV) {
                    int b = row >> 11, s = row & 2047;
                    int which = col >> 10;
                    int h = (col >> 6) & 15;
                    int dh = col & 63;
                    float* dst = (which == 0) ? g_q : (which == 1) ? g_k : g_v;
                    *reinterpret_cast<float2*>(
                        &dst[(((long)(b*NHEAD + h))*S_LEN + s)*DHEAD + dh]) = v;
                } else {
                    *reinterpret_cast<float2*>(&Out[(long)row*N + col]) = v;
                }
            }
        }
    }
}

#define GEMM_SMEM_BYTES (8 * PLANE * (int)sizeof(__nv_bfloat16))  // 80KB

// ---------------------------------------------------------------------------
// Kernel B: banded attention. Per (b,h), 64-query tile; keys in
// [qstart-128, qstart+63] (192 keys). S tile OVERLAYS the K tile (dead after
// QK^T) -> 112KB smem -> 2 CTAs/SM.
// ---------------------------------------------------------------------------
#define ATTN_SMEM_FLOATS (4096 + 12288 + 12288)

__global__ __launch_bounds__(256)
void attn_kernel(const float* __restrict__ bias)
{
    extern __shared__ float sm[];
    float* Qs = sm;                       // [64][64]
    float* Ks = sm + 4096;                // [192][64]  (becomes Ss [64][192])
    float* Vs = sm + 4096 + 12288;        // [192][64]
    float* Ss = Ks;                       // overlay

    const int tid = threadIdx.x;
    const int qt = blockIdx.x;
    const int bh = blockIdx.y;
    const int qstart = qt * 64;
    const int jbase = qstart - 128;

    const float* qg = g_q + (long)bh * S_LEN * DHEAD;
    const float* kg = g_k + (long)bh * S_LEN * DHEAD;
    const float* vg = g_v + (long)bh * S_LEN * DHEAD;

    for (int idx = tid; idx < 64*64; idx += 256)
        Qs[idx] = qg[(long)(qstart + (idx >> 6))*DHEAD + (idx & 63)];
    for (int idx = tid; idx < 192*64; idx += 256) {
        int j = jbase + (idx >> 6);
        float kv = 0.f, vv = 0.f;
        if (j >= 0) {
            kv = kg[(long)j*DHEAD + (idx & 63)];
            vv = vg[(long)j*DHEAD + (idx & 63)];
        }
        Ks[idx] = kv; Vs[idx] = vv;
    }
    __syncthreads();

    const int ty = tid >> 4, tx = tid & 15;

    // ---- Phase 1: S = Q K^T + scale + bias + masks ----
    {
        float acc[4][12];
        #pragma unroll
        for (int i = 0; i < 4; i++)
            #pragma unroll
            for (int j = 0; j < 12; j++) acc[i][j] = 0.f;

        for (int k = 0; k < 64; k++) {
            float rq[4], rk[12];
            #pragma unroll
            for (int i = 0; i < 4; i++) rq[i] = Qs[(ty*4+i)*64 + k];
            #pragma unroll
            for (int j = 0; j < 12; j++) rk[j] = Ks[(tx*12+j)*64 + k];
            #pragma unroll
            for (int i = 0; i < 4; i++)
                #pragma unroll
                for (int j = 0; j < 12; j++)
                    acc[i][j] = fmaf(rq[i], rk[j], acc[i][j]);
        }
        __syncthreads();   // all K reads done before S overlays it

        const float scale = 0.125f;
        const float* bb = bias + (long)bh * S_LEN * S_LEN;
        #pragma unroll
        for (int i = 0; i < 4; i++) {
            int gi = qstart + ty*4 + i;
            #pragma unroll
            for (int j = 0; j < 12; j++) {
                int c = tx*12 + j;
                int gj = jbase + c;
                float val = NEGBIG;
                if (gj >= 0 && gj <= gi && (gi - gj) <= 128)
                    val = acc[i][j]*scale + bb[(long)gi*S_LEN + gj];
                Ss[(ty*4+i)*192 + c] = val;
            }
        }
    }
    __syncthreads();

    // ---- Phase 2: row softmax ----
    {
        const int w = tid >> 5, lane = tid & 31;
        for (int rr = 0; rr < 8; rr++) {
            int r = w*8 + rr;
            float vals[6];
            float m = NEGBIG;
            #pragma unroll
            for (int t = 0; t < 6; t++) {
                vals[t] = Ss[r*192 + t*32 + lane];
                m = fmaxf(m, vals[t]);
            }
            #pragma unroll
            for (int o = 16; o > 0; o >>= 1)
                m = fmaxf(m, __shfl_xor_sync(0xffffffffu, m, o));
            float ssum = 0.f;
            #pragma unroll
            for (int t = 0; t < 6; t++) {
                vals[t] = __expf(vals[t] - m);
                ssum += vals[t];
            }
            #pragma unroll
            for (int o = 16; o > 0; o >>= 1)
                ssum += __shfl_xor_sync(0xffffffffu, ssum, o);
            float inv = 1.f / ssum;
            #pragma unroll
            for (int t = 0; t < 6; t++)
                Ss[r*192 + t*32 + lane] = vals[t] * inv;
        }
    }
    __syncthreads();

    // ---- Phase 3: O = P V ----
    {
        float acc[4][4];
        #pragma unroll
        for (int i = 0; i < 4; i++)
            #pragma unroll
            for (int j = 0; j < 4; j++) acc[i][j] = 0.f;

        for (int k = 0; k < 192; k++) {
            float rp[4], rv[4];
            #pragma unroll
            for (int i = 0; i < 4; i++) rp[i] = Ss[(ty*4+i)*192 + k];
            #pragma unroll
            for (int j = 0; j < 4; j++) rv[j] = Vs[k*64 + tx*4 + j];
            #pragma unroll
            for (int i = 0; i < 4; i++)
                #pragma unroll
                for (int j = 0; j < 4; j++)
                    acc[i][j] = fmaf(rp[i], rv[j], acc[i][j]);
        }

        const int b = bh >> 4, h = bh & 15;
        #pragma unroll
        for (int i = 0; i < 4; i++) {
            int gi = qstart + ty*4 + i;
            #pragma unroll
            for (int j = 0; j < 4; j++) {
                g_att[((long)(b*S_LEN + gi))*D_MODEL + h*DHEAD + tx*4 + j] = acc[i][j];
            }
        }
    }
}

// ---------------------------------------------------------------------------
extern "C" void kernel_launch(void* const* d_in, const int* in_sizes, int n_in,
                              void* d_out, int out_size)
{
    const float* x    = (const float*)d_in[0];
    const float* bias = (const float*)d_in[1];
    // d_in[2] = causal mask (recomputed analytically in-kernel)
    const float* Wqkv = (const float*)d_in[3];
    const float* Wout = (const float*)d_in[4];
    float* out = (float*)d_out;

    cudaFuncSetAttribute(bf16_gemm_kernel<3072, true>,
                         cudaFuncAttributeMaxDynamicSharedMemorySize, GEMM_SMEM_BYTES);
    cudaFuncSetAttribute(bf16_gemm_kernel<1024, false>,
                         cudaFuncAttributeMaxDynamicSharedMemorySize, GEMM_SMEM_BYTES);
    cudaFuncSetAttribute(attn_kernel,
                         cudaFuncAttributeMaxDynamicSharedMemorySize,
                         ATTN_SMEM_FLOATS * (int)sizeof(float));

    // A: QKV projection (M=4096, N=3072), 3xBF16 tensor-core GEMM
    bf16_gemm_kernel<3072, true><<<dim3(24, 32), 256, GEMM_SMEM_BYTES>>>(x, Wqkv, nullptr);

    // B: banded attention (32 q-tiles x 32 (b,h)), 112KB smem -> 2 CTA/SM
    attn_kernel<<<dim3(32, 32), 256, ATTN_SMEM_FLOATS * (int)sizeof(float)>>>(bias);

    // C: output projection (M=4096, N=1024), 3xBF16 tensor-core GEMM
    bf16_gemm_kernel<1024, false><<<dim3(8, 32), 256, GEMM_SMEM_BYTES>>>(nullptr, Wout, out);
}

// round 4
// speedup vs baseline: 2.3481x; 2.3481x over previous
#include <cuda_runtime.h>
#include <cuda_bf16.h>
#include <math.h>
#include <stdint.h>

#define BATCH 2
#define S_LEN 2048
#define D_MODEL 1024
#define NHEAD 16
#define DHEAD 64
#define NEGBIG -1e30f

// fp32 scratch
__device__ float g_q[BATCH*NHEAD*S_LEN*DHEAD];
__device__ float g_k[BATCH*NHEAD*S_LEN*DHEAD];
__device__ float g_v[BATCH*NHEAD*S_LEN*DHEAD];
__device__ float g_att[BATCH*S_LEN*D_MODEL];

// bf16 hi/lo planes
__device__ __nv_bfloat16 g_xh[4096*1024],  g_xl[4096*1024];
__device__ __nv_bfloat16 g_ath[4096*1024], g_atl[4096*1024];
__device__ __nv_bfloat16 g_wqh[3072*1024], g_wql[3072*1024];   // transposed N x K
__device__ __nv_bfloat16 g_woh[1024*1024], g_wol[1024*1024];   // transposed N x K

__device__ __forceinline__ void bf16split(float x, __nv_bfloat16& hi, __nv_bfloat16& lo) {
    hi = __float2bfloat16_rn(x);
    lo = __float2bfloat16_rn(x - __bfloat162float(hi));
}

// ---------------------------------------------------------------------------
// Pre-pass 1: elementwise split (row-major preserved). n = total elements /4.
// ---------------------------------------------------------------------------
__global__ void split_plain_kernel(const float* __restrict__ in,
                                   __nv_bfloat16* __restrict__ hi,
                                   __nv_bfloat16* __restrict__ lo)
{
    int i = (blockIdx.x * 256 + threadIdx.x) * 4;
    float4 v = *reinterpret_cast<const float4*>(in + i);
    __nv_bfloat16 h0,l0,h1,l1,h2,l2,h3,l3;
    bf16split(v.x,h0,l0); bf16split(v.y,h1,l1);
    bf16split(v.z,h2,l2); bf16split(v.w,h3,l3);
    *reinterpret_cast<__nv_bfloat162*>(hi + i)     = __nv_bfloat162(h0,h1);
    *reinterpret_cast<__nv_bfloat162*>(hi + i + 2) = __nv_bfloat162(h2,h3);
    *reinterpret_cast<__nv_bfloat162*>(lo + i)     = __nv_bfloat162(l0,l1);
    *reinterpret_cast<__nv_bfloat162*>(lo + i + 2) = __nv_bfloat162(l2,l3);
}

// ---------------------------------------------------------------------------
// Pre-pass 2: split + transpose. in: R x C (fp32) -> hiT/loT: C x R (bf16).
// Block (32,8), 32x32 tile.
// ---------------------------------------------------------------------------
__global__ void transpose_split_kernel(const float* __restrict__ in,
                                       __nv_bfloat16* __restrict__ hiT,
                                       __nv_bfloat16* __restrict__ loT,
                                       int R, int C)
{
    __shared__ float t[32][33];
    const int tx = threadIdx.x, ty = threadIdx.y;
    const int r0 = blockIdx.y * 32, c0 = blockIdx.x * 32;
    #pragma unroll
    for (int i = 0; i < 4; i++)
        t[ty + i*8][tx] = in[(long)(r0 + ty + i*8) * C + c0 + tx];
    __syncthreads();
    #pragma unroll
    for (int i = 0; i < 4; i++) {
        float v = t[tx][ty + i*8];
        __nv_bfloat16 h, l;
        bf16split(v, h, l);
        long o = (long)(c0 + ty + i*8) * R + r0 + tx;
        hiT[o] = h; loT[o] = l;
    }
}

// ---------------------------------------------------------------------------
// bf16 3-term GEMM: C = A(MxK) @ B^T(NxK), K=1024, planes precomputed.
// BM=BN=128, BK=32, 256 thr, 8 warps 4x2 (32x64 warp tiles), cp.async x2.
// smem: 4 planes x 2 buf x 128x40 bf16 = 80KB.
// ---------------------------------------------------------------------------
#define KP 40
#define GPLANE (128*KP)
#define GEMM_SMEM_BYTES (8 * GPLANE * (int)sizeof(__nv_bfloat16))

__device__ __forceinline__ void cpasync16(__nv_bfloat16* smem, const __nv_bfloat16* g) {
    uint32_t s = (uint32_t)__cvta_generic_to_shared(smem);
    asm volatile("cp.async.cg.shared.global [%0], [%1], 16;\n" :: "r"(s), "l"(g));
}

__device__ __forceinline__ void mma_bf16(float* c, const uint32_t* a, const uint32_t* b) {
    asm volatile(
        "mma.sync.aligned.m16n8k16.row.col.f32.bf16.bf16.f32 "
        "{%0,%1,%2,%3}, {%4,%5,%6,%7}, {%8,%9}, {%0,%1,%2,%3};"
        : "+f"(c[0]), "+f"(c[1]), "+f"(c[2]), "+f"(c[3])
        : "r"(a[0]), "r"(a[1]), "r"(a[2]), "r"(a[3]), "r"(b[0]), "r"(b[1]));
}

template<int N, bool IS_QKV>
__global__ __launch_bounds__(256)
void bf16_gemm_kernel(const __nv_bfloat16* __restrict__ Ahg,
                      const __nv_bfloat16* __restrict__ Alg,
                      const __nv_bfloat16* __restrict__ Bhg,
                      const __nv_bfloat16* __restrict__ Blg,
                      float* __restrict__ Out)
{
    extern __shared__ __nv_bfloat16 smg[];
    __nv_bfloat16* Ah = smg;
    __nv_bfloat16* Al = smg + 2*GPLANE;
    __nv_bfloat16* Bh = smg + 4*GPLANE;
    __nv_bfloat16* Bl = smg + 6*GPLANE;

    const int K = 1024;
    const int tid  = threadIdx.x;
    const int lane = tid & 31;
    const int wid  = tid >> 5;
    const int wm   = wid & 3;
    const int wn   = wid >> 2;
    const int m0 = blockIdx.y * 128;
    const int n0 = blockIdx.x * 128;

    float acc[2][8][4];
    #pragma unroll
    for (int mt = 0; mt < 2; mt++)
        #pragma unroll
        for (int nt = 0; nt < 8; nt++)
            #pragma unroll
            for (int i = 0; i < 4; i++) acc[mt][nt][i] = 0.f;

    // loader: 512 16B-chunks per plane-tile (128 rows x 32 bf16); 2/thread
    auto load_tiles = [&](int k0, int buf) {
        #pragma unroll
        for (int u = 0; u < 2; u++) {
            int c = tid + u*256;
            int row = c >> 2, kc = (c & 3) * 8;
            long go = (long)(m0 + row)*K + k0 + kc;
            cpasync16(&Ah[buf*GPLANE + row*KP + kc], Ahg + go);
            cpasync16(&Al[buf*GPLANE + row*KP + kc], Alg + go);
        }
        #pragma unroll
        for (int u = 0; u < 2; u++) {
            int c = tid + u*256;
            int row = c >> 2, kc = (c & 3) * 8;
            long go = (long)(n0 + row)*K + k0 + kc;
            cpasync16(&Bh[buf*GPLANE + row*KP + kc], Bhg + go);
            cpasync16(&Bl[buf*GPLANE + row*KP + kc], Blg + go);
        }
        asm volatile("cp.async.commit_group;\n");
    };

    load_tiles(0, 0);

    const int NIT = K / 32;
    for (int it = 0; it < NIT; ++it) {
        const int buf = it & 1;
        asm volatile("cp.async.wait_group 0;\n");
        __syncthreads();
        if (it + 1 < NIT) load_tiles((it+1)*32, buf ^ 1);

        const __nv_bfloat16* ah_ = Ah + buf*GPLANE;
        const __nv_bfloat16* al_ = Al + buf*GPLANE;
        const __nv_bfloat16* bh_ = Bh + buf*GPLANE;
        const __nv_bfloat16* bl_ = Bl + buf*GPLANE;

        #pragma unroll
        for (int ks = 0; ks < 2; ks++) {
            const int kb = ks*16 + (lane & 3)*2;
            uint32_t ahf[2][4], alf[2][4];
            #pragma unroll
            for (int mt = 0; mt < 2; mt++) {
                int r = wm*32 + mt*16 + (lane >> 2);
                ahf[mt][0] = *reinterpret_cast<const uint32_t*>(&ah_[r*KP + kb]);
                ahf[mt][1] = *reinterpret_cast<const uint32_t*>(&ah_[(r+8)*KP + kb]);
                ahf[mt][2] = *reinterpret_cast<const uint32_t*>(&ah_[r*KP + kb + 8]);
                ahf[mt][3] = *reinterpret_cast<const uint32_t*>(&ah_[(r+8)*KP + kb + 8]);
                alf[mt][0] = *reinterpret_cast<const uint32_t*>(&al_[r*KP + kb]);
                alf[mt][1] = *reinterpret_cast<const uint32_t*>(&al_[(r+8)*KP + kb]);
                alf[mt][2] = *reinterpret_cast<const uint32_t*>(&al_[r*KP + kb + 8]);
                alf[mt][3] = *reinterpret_cast<const uint32_t*>(&al_[(r+8)*KP + kb + 8]);
            }
            uint32_t bhf[8][2], blf[8][2];
            #pragma unroll
            for (int nt = 0; nt < 8; nt++) {
                int c = wn*64 + nt*8 + (lane >> 2);
                bhf[nt][0] = *reinterpret_cast<const uint32_t*>(&bh_[c*KP + kb]);
                bhf[nt][1] = *reinterpret_cast<const uint32_t*>(&bh_[c*KP + kb + 8]);
                blf[nt][0] = *reinterpret_cast<const uint32_t*>(&bl_[c*KP + kb]);
                blf[nt][1] = *reinterpret_cast<const uint32_t*>(&bl_[c*KP + kb + 8]);
            }
            #pragma unroll
            for (int mt = 0; mt < 2; mt++)
                #pragma unroll
                for (int nt = 0; nt < 8; nt++) {
                    mma_bf16(acc[mt][nt], ahf[mt], blf[nt]);  // hi*lo
                    mma_bf16(acc[mt][nt], alf[mt], bhf[nt]);  // lo*hi
                    mma_bf16(acc[mt][nt], ahf[mt], bhf[nt]);  // hi*hi
                }
        }
        __syncthreads();
    }

    #pragma unroll
    for (int mt = 0; mt < 2; mt++) {
        #pragma unroll
        for (int i = 0; i < 2; i++) {
            int row = m0 + wm*32 + mt*16 + (lane >> 2) + i*8;
            #pragma unroll
            for (int nt = 0; nt < 8; nt++) {
                int col = n0 + wn*64 + nt*8 + (lane & 3)*2;
                float2 v = make_float2(acc[mt][nt][i*2+0], acc[mt][nt][i*2+1]);
                if (IS_QKV) {
                    int b = row >> 11, s = row & 2047;
                    int which = col >> 10;
                    int h = (col >> 6) & 15;
                    int dh = col & 63;
                    float* dst = (which == 0) ? g_q : (which == 1) ? g_k : g_v;
                    *reinterpret_cast<float2*>(
                        &dst[(((long)(b*NHEAD + h))*S_LEN + s)*DHEAD + dh]) = v;
                } else {
                    *reinterpret_cast<float2*>(&Out[(long)row*N + col]) = v;
                }
            }
        }
    }
}

// ---------------------------------------------------------------------------
// Banded attention. Qs pitch 65, Ks pitch 65 (kills the 16-way rk conflict),
// Vs pitch 64. S (64x192) overlays Ks. smem 113KB -> 2 CTAs/SM.
// ---------------------------------------------------------------------------
#define QS_P 65
#define KS_P 65
#define ATTN_SMEM_FLOATS (64*QS_P + 192*KS_P + 192*64)

__global__ __launch_bounds__(256)
void attn_kernel(const float* __restrict__ bias)
{
    extern __shared__ float sm[];
    float* Qs = sm;                         // [64][65]
    float* Ks = sm + 64*QS_P;               // [192][65], becomes Ss [64][192]
    float* Vs = sm + 64*QS_P + 192*KS_P;    // [192][64]
    float* Ss = Ks;

    const int tid = threadIdx.x;
    const int qt = blockIdx.x;
    const int bh = blockIdx.y;
    const int qstart = qt * 64;
    const int jbase = qstart - 128;

    const float* qg = g_q + (long)bh * S_LEN * DHEAD;
    const float* kg = g_k + (long)bh * S_LEN * DHEAD;
    const float* vg = g_v + (long)bh * S_LEN * DHEAD;

    for (int idx = tid; idx < 64*64; idx += 256)
        Qs[(idx >> 6)*QS_P + (idx & 63)] = qg[(long)(qstart + (idx >> 6))*DHEAD + (idx & 63)];
    for (int idx = tid; idx < 192*64; idx += 256) {
        int j = jbase + (idx >> 6);
        float kv = 0.f, vv = 0.f;
        if (j >= 0) {
            kv = kg[(long)j*DHEAD + (idx & 63)];
            vv = vg[(long)j*DHEAD + (idx & 63)];
        }
        Ks[(idx >> 6)*KS_P + (idx & 63)] = kv;
        Vs[idx] = vv;
    }
    __syncthreads();

    const int ty = tid >> 4, tx = tid & 15;

    // ---- Phase 1: S = Q K^T + scale + bias + masks ----
    {
        float acc[4][12];
        #pragma unroll
        for (int i = 0; i < 4; i++)
            #pragma unroll
            for (int j = 0; j < 12; j++) acc[i][j] = 0.f;

        #pragma unroll 4
        for (int k = 0; k < 64; k++) {
            float rq[4], rk[12];
            #pragma unroll
            for (int i = 0; i < 4; i++) rq[i] = Qs[(ty*4+i)*QS_P + k];
            #pragma unroll
            for (int j = 0; j < 12; j++) rk[j] = Ks[(tx*12+j)*KS_P + k];
            #pragma unroll
            for (int i = 0; i < 4; i++)
                #pragma unroll
                for (int j = 0; j < 12; j++)
                    acc[i][j] = fmaf(rq[i], rk[j], acc[i][j]);
        }
        __syncthreads();   // finish all K reads before S overlays Ks

        const float scale = 0.125f;
        const float* bb = bias + (long)bh * S_LEN * S_LEN;
        #pragma unroll
        for (int i = 0; i < 4; i++) {
            int gi = qstart + ty*4 + i;
            #pragma unroll
            for (int j = 0; j < 12; j++) {
                int c = tx*12 + j;
                int gj = jbase + c;
                float val = NEGBIG;
                if (gj >= 0 && gj <= gi && (gi - gj) <= 128)
                    val = acc[i][j]*scale + bb[(long)gi*S_LEN + gj];
                Ss[(ty*4+i)*192 + c] = val;
            }
        }
    }
    __syncthreads();

    // ---- Phase 2: row softmax ----
    {
        const int w = tid >> 5, lane = tid & 31;
        for (int rr = 0; rr < 8; rr++) {
            int r = w*8 + rr;
            float vals[6];
            float m = NEGBIG;
            #pragma unroll
            for (int t = 0; t < 6; t++) {
                vals[t] = Ss[r*192 + t*32 + lane];
                m = fmaxf(m, vals[t]);
            }
            #pragma unroll
            for (int o = 16; o > 0; o >>= 1)
                m = fmaxf(m, __shfl_xor_sync(0xffffffffu, m, o));
            float ssum = 0.f;
            #pragma unroll
            for (int t = 0; t < 6; t++) {
                vals[t] = __expf(vals[t] - m);
                ssum += vals[t];
            }
            #pragma unroll
            for (int o = 16; o > 0; o >>= 1)
                ssum += __shfl_xor_sync(0xffffffffu, ssum, o);
            float inv = 1.f / ssum;
            #pragma unroll
            for (int t = 0; t < 6; t++)
                Ss[r*192 + t*32 + lane] = vals[t] * inv;
        }
    }
    __syncthreads();

    // ---- Phase 3: O = P V ----
    {
        float acc[4][4];
        #pragma unroll
        for (int i = 0; i < 4; i++)
            #pragma unroll
            for (int j = 0; j < 4; j++) acc[i][j] = 0.f;

        #pragma unroll 4
        for (int k = 0; k < 192; k++) {
            float rp[4], rv[4];
            #pragma unroll
            for (int i = 0; i < 4; i++) rp[i] = Ss[(ty*4+i)*192 + k];
            #pragma unroll
            for (int j = 0; j < 4; j++) rv[j] = Vs[k*64 + tx*4 + j];
            #pragma unroll
            for (int i = 0; i < 4; i++)
                #pragma unroll
                for (int j = 0; j < 4; j++)
                    acc[i][j] = fmaf(rp[i], rv[j], acc[i][j]);
        }

        const int b = bh >> 4, h = bh & 15;
        #pragma unroll
        for (int i = 0; i < 4; i++) {
            int gi = qstart + ty*4 + i;
            #pragma unroll
            for (int j = 0; j < 4; j++) {
                g_att[((long)(b*S_LEN + gi))*D_MODEL + h*DHEAD + tx*4 + j] = acc[i][j];
            }
        }
    }
}

// ---------------------------------------------------------------------------
extern "C" void kernel_launch(void* const* d_in, const int* in_sizes, int n_in,
                              void* d_out, int out_size)
{
    const float* x    = (const float*)d_in[0];
    const float* bias = (const float*)d_in[1];
    // d_in[2] = causal mask (recomputed analytically in-kernel)
    const float* Wqkv = (const float*)d_in[3];
    const float* Wout = (const float*)d_in[4];
    float* out = (float*)d_out;

    __nv_bfloat16 *xh, *xl, *ath, *atl, *wqh, *wql, *woh, *wol;
    cudaGetSymbolAddress((void**)&xh,  g_xh);  cudaGetSymbolAddress((void**)&xl,  g_xl);
    cudaGetSymbolAddress((void**)&ath, g_ath); cudaGetSymbolAddress((void**)&atl, g_atl);
    cudaGetSymbolAddress((void**)&wqh, g_wqh); cudaGetSymbolAddress((void**)&wql, g_wql);
    cudaGetSymbolAddress((void**)&woh, g_woh); cudaGetSymbolAddress((void**)&wol, g_wol);
    float* att; cudaGetSymbolAddress((void**)&att, g_att);

    cudaFuncSetAttribute(bf16_gemm_kernel<3072, true>,
                         cudaFuncAttributeMaxDynamicSharedMemorySize, GEMM_SMEM_BYTES);
    cudaFuncSetAttribute(bf16_gemm_kernel<1024, false>,
                         cudaFuncAttributeMaxDynamicSharedMemorySize, GEMM_SMEM_BYTES);
    cudaFuncSetAttribute(attn_kernel,
                         cudaFuncAttributeMaxDynamicSharedMemorySize,
                         ATTN_SMEM_FLOATS * (int)sizeof(float));

    // Pre-passes: split x; split+transpose weights
    split_plain_kernel<<<4096, 256>>>(x, xh, xl);
    transpose_split_kernel<<<dim3(3072/32, 1024/32), dim3(32, 8)>>>(Wqkv, wqh, wql, 1024, 3072);
    transpose_split_kernel<<<dim3(1024/32, 1024/32), dim3(32, 8)>>>(Wout, woh, wol, 1024, 1024);

    // QKV projection (M=4096, N=3072)
    bf16_gemm_kernel<3072, true><<<dim3(24, 32), 256, GEMM_SMEM_BYTES>>>(
        xh, xl, wqh, wql, nullptr);

    // Banded attention
    attn_kernel<<<dim3(32, 32), 256, ATTN_SMEM_FLOATS * (int)sizeof(float)>>>(bias);

    // Split attention output, then output projection (M=4096, N=1024)
    split_plain_kernel<<<4096, 256>>>(att, ath, atl);
    bf16_gemm_kernel<1024, false><<<dim3(8, 32), 256, GEMM_SMEM_BYTES>>>(
        ath, atl, woh, wol, out);
}

// round 7
// speedup vs baseline: 3.5167x; 1.4977x over previous
#include <cuda_runtime.h>
#include <cuda_bf16.h>
#include <math.h>
#include <stdint.h>

#define BATCH 2
#define S_LEN 2048
#define D_MODEL 1024
#define NHEAD 16
#define DHEAD 64
#define NEGBIG -1e30f

// fp32 scratch
__device__ float g_q[BATCH*NHEAD*S_LEN*DHEAD];
__device__ float g_k[BATCH*NHEAD*S_LEN*DHEAD];
__device__ float g_v[BATCH*NHEAD*S_LEN*DHEAD];
__device__ float g_att[BATCH*S_LEN*D_MODEL];

// bf16 hi/lo planes
__device__ __nv_bfloat16 g_xh[4096*1024],  g_xl[4096*1024];
__device__ __nv_bfloat16 g_ath[4096*1024], g_atl[4096*1024];
__device__ __nv_bfloat16 g_wqh[3072*1024], g_wql[3072*1024];   // transposed N x K
__device__ __nv_bfloat16 g_woh[1024*1024], g_wol[1024*1024];   // transposed N x K

__device__ __forceinline__ void bf16split(float x, __nv_bfloat16& hi, __nv_bfloat16& lo) {
    hi = __float2bfloat16_rn(x);
    lo = __float2bfloat16_rn(x - __bfloat162float(hi));
}

// ---------------------------------------------------------------------------
// Pre-pass 1: elementwise split (row-major preserved)
// ---------------------------------------------------------------------------
__global__ void split_plain_kernel(const float* __restrict__ in,
                                   __nv_bfloat16* __restrict__ hi,
                                   __nv_bfloat16* __restrict__ lo)
{
    int i = (blockIdx.x * 256 + threadIdx.x) * 4;
    float4 v = *reinterpret_cast<const float4*>(in + i);
    __nv_bfloat16 h0,l0,h1,l1,h2,l2,h3,l3;
    bf16split(v.x,h0,l0); bf16split(v.y,h1,l1);
    bf16split(v.z,h2,l2); bf16split(v.w,h3,l3);
    *reinterpret_cast<__nv_bfloat162*>(hi + i)     = __nv_bfloat162(h0,h1);
    *reinterpret_cast<__nv_bfloat162*>(hi + i + 2) = __nv_bfloat162(h2,h3);
    *reinterpret_cast<__nv_bfloat162*>(lo + i)     = __nv_bfloat162(l0,l1);
    *reinterpret_cast<__nv_bfloat162*>(lo + i + 2) = __nv_bfloat162(l2,l3);
}

// ---------------------------------------------------------------------------
// Pre-pass 2: split + transpose. in: R x C (fp32) -> hiT/loT: C x R (bf16)
// ---------------------------------------------------------------------------
__global__ void transpose_split_kernel(const float* __restrict__ in,
                                       __nv_bfloat16* __restrict__ hiT,
                                       __nv_bfloat16* __restrict__ loT,
                                       int R, int C)
{
    __shared__ float t[32][33];
    const int tx = threadIdx.x, ty = threadIdx.y;
    const int r0 = blockIdx.y * 32, c0 = blockIdx.x * 32;
    #pragma unroll
    for (int i = 0; i < 4; i++)
        t[ty + i*8][tx] = in[(long)(r0 + ty + i*8) * C + c0 + tx];
    __syncthreads();
    #pragma unroll
    for (int i = 0; i < 4; i++) {
        float v = t[tx][ty + i*8];
        __nv_bfloat16 h, l;
        bf16split(v, h, l);
        long o = (long)(c0 + ty + i*8) * R + r0 + tx;
        hiT[o] = h; loT[o] = l;
    }
}

// ---------------------------------------------------------------------------
// bf16 3-term GEMM with ldmatrix fragment loads.
// C = A(MxK) @ B^T(NxK), K=1024. BM=BN=128, BK=32, 256 thr, 8 warps (4x2),
// cp.async double buffer. Planes Ah/Al/Bh/Bl pitch 40 bf16 -> 80KB smem.
// ---------------------------------------------------------------------------
#define KP 40
#define GPLANE (128*KP)
#define GEMM_SMEM_BYTES (8 * GPLANE * (int)sizeof(__nv_bfloat16))

__device__ __forceinline__ void cpasync16(__nv_bfloat16* smem, const __nv_bfloat16* g) {
    uint32_t s = (uint32_t)__cvta_generic_to_shared(smem);
    asm volatile("cp.async.cg.shared.global [%0], [%1], 16;\n" :: "r"(s), "l"(g));
}

__device__ __forceinline__ void mma_bf16(float* c, const uint32_t* a, const uint32_t* b) {
    asm volatile(
        "mma.sync.aligned.m16n8k16.row.col.f32.bf16.bf16.f32 "
        "{%0,%1,%2,%3}, {%4,%5,%6,%7}, {%8,%9}, {%0,%1,%2,%3};"
        : "+f"(c[0]), "+f"(c[1]), "+f"(c[2]), "+f"(c[3])
        : "r"(a[0]), "r"(a[1]), "r"(a[2]), "r"(a[3]), "r"(b[0]), "r"(b[1]));
}

__device__ __forceinline__ void ldsm_x4(uint32_t* r, uint32_t addr) {
    asm volatile("ldmatrix.sync.aligned.m8n8.x4.shared.b16 {%0,%1,%2,%3}, [%4];"
                 : "=r"(r[0]), "=r"(r[1]), "=r"(r[2]), "=r"(r[3]) : "r"(addr));
}

template<int N, bool IS_QKV>
__global__ __launch_bounds__(256)
void bf16_gemm_kernel(const __nv_bfloat16* __restrict__ Ahg,
                      const __nv_bfloat16* __restrict__ Alg,
                      const __nv_bfloat16* __restrict__ Bhg,
                      const __nv_bfloat16* __restrict__ Blg,
                      float* __restrict__ Out)
{
    extern __shared__ __nv_bfloat16 smg[];
    __nv_bfloat16* Ah = smg;
    __nv_bfloat16* Al = smg + 2*GPLANE;
    __nv_bfloat16* Bh = smg + 4*GPLANE;
    __nv_bfloat16* Bl = smg + 6*GPLANE;

    const int K = 1024;
    const int tid  = threadIdx.x;
    const int lane = tid & 31;
    const int wid  = tid >> 5;
    const int wm   = wid & 3;
    const int wn   = wid >> 2;
    const int m0 = blockIdx.y * 128;
    const int n0 = blockIdx.x * 128;

    // ldmatrix per-lane offset (shared by A and B tiles):
    // lanes 0-7: rows 0-7 @k, 8-15: rows 8-15 @k, 16-23: rows 0-7 @k+8,
    // 24-31: rows 8-15 @k+8.
    const int lrow = ((lane >> 3) & 1) * 8 + (lane & 7);
    const int lkq  = (lane >> 4) * 8;
    const uint32_t lmo = (uint32_t)((lrow * KP + lkq) * 2);   // bytes

    const uint32_t sAh = (uint32_t)__cvta_generic_to_shared(Ah);
    const uint32_t sAl = sAh + 2*GPLANE*2;
    const uint32_t sBh = sAh + 4*GPLANE*2;
    const uint32_t sBl = sAh + 6*GPLANE*2;

    float acc[2][8][4];
    #pragma unroll
    for (int mt = 0; mt < 2; mt++)
        #pragma unroll
        for (int nt = 0; nt < 8; nt++)
            #pragma unroll
            for (int i = 0; i < 4; i++) acc[mt][nt][i] = 0.f;

    auto load_tiles = [&](int k0, int buf) {
        #pragma unroll
        for (int u = 0; u < 2; u++) {
            int c = tid + u*256;
            int row = c >> 2, kc = (c & 3) * 8;
            long go = (long)(m0 + row)*K + k0 + kc;
            cpasync16(&Ah[buf*GPLANE + row*KP + kc], Ahg + go);
            cpasync16(&Al[buf*GPLANE + row*KP + kc], Alg + go);
        }
        #pragma unroll
        for (int u = 0; u < 2; u++) {
            int c = tid + u*256;
            int row = c >> 2, kc = (c & 3) * 8;
            long go = (long)(n0 + row)*K + k0 + kc;
            cpasync16(&Bh[buf*GPLANE + row*KP + kc], Bhg + go);
            cpasync16(&Bl[buf*GPLANE + row*KP + kc], Blg + go);
        }
        asm volatile("cp.async.commit_group;\n");
    };

    load_tiles(0, 0);

    const int NIT = K / 32;
    for (int it = 0; it < NIT; ++it) {
        const int buf = it & 1;
        asm volatile("cp.async.wait_group 0;\n");
        __syncthreads();
        if (it + 1 < NIT) load_tiles((it+1)*32, buf ^ 1);

        const uint32_t bofs = (uint32_t)(buf*GPLANE*2);

        #pragma unroll
        for (int ks = 0; ks < 2; ks++) {
            const uint32_t kbo = bofs + (uint32_t)(ks*16*2) + lmo;

            uint32_t ahf[2][4], alf[2][4];
            #pragma unroll
            for (int mt = 0; mt < 2; mt++) {
                uint32_t ro = (uint32_t)((wm*32 + mt*16) * KP * 2);
                ldsm_x4(ahf[mt], sAh + ro + kbo);
                ldsm_x4(alf[mt], sAl + ro + kbo);
            }
            // B: each x4 serves a pair of n-tiles (nt=2p, 2p+1)
            uint32_t bhf[8][2], blf[8][2];
            #pragma unroll
            for (int p = 0; p < 4; p++) {
                uint32_t ro = (uint32_t)((wn*64 + p*16) * KP * 2);
                uint32_t r[4];
                ldsm_x4(r, sBh + ro + kbo);
                bhf[2*p+0][0] = r[0]; bhf[2*p+1][0] = r[1];
                bhf[2*p+0][1] = r[2]; bhf[2*p+1][1] = r[3];
                ldsm_x4(r, sBl + ro + kbo);
                blf[2*p+0][0] = r[0]; blf[2*p+1][0] = r[1];
                blf[2*p+0][1] = r[2]; blf[2*p+1][1] = r[3];
            }
            #pragma unroll
            for (int mt = 0; mt < 2; mt++)
                #pragma unroll
                for (int nt = 0; nt < 8; nt++) {
                    mma_bf16(acc[mt][nt], ahf[mt], blf[nt]);  // hi*lo
                    mma_bf16(acc[mt][nt], alf[mt], bhf[nt]);  // lo*hi
                    mma_bf16(acc[mt][nt], ahf[mt], bhf[nt]);  // hi*hi
                }
        }
        __syncthreads();
    }

    #pragma unroll
    for (int mt = 0; mt < 2; mt++) {
        #pragma unroll
        for (int i = 0; i < 2; i++) {
            int row = m0 + wm*32 + mt*16 + (lane >> 2) + i*8;
            #pragma unroll
            for (int nt = 0; nt < 8; nt++) {
                int col = n0 + wn*64 + nt*8 + (lane & 3)*2;
                float2 v = make_float2(acc[mt][nt][i*2+0], acc[mt][nt][i*2+1]);
                if (IS_QKV) {
                    int b = row >> 11, s = row & 2047;
                    int which = col >> 10;
                    int h = (col >> 6) & 15;
                    int dh = col & 63;
                    float* dst = (which == 0) ? g_q : (which == 1) ? g_k : g_v;
                    *reinterpret_cast<float2*>(
                        &dst[(((long)(b*NHEAD + h))*S_LEN + s)*DHEAD + dh]) = v;
                } else {
                    *reinterpret_cast<float2*>(&Out[(long)row*N + col]) = v;
                }
            }
        }
    }
}

// ---------------------------------------------------------------------------
// Banded attention (R4 layout): Qs/Ks pitch 65, S overlays K. 2 CTAs/SM.
// ---------------------------------------------------------------------------
#define QS_P 65
#define KS_P 65
#define ATTN_SMEM_FLOATS (64*QS_P + 192*KS_P + 192*64)

__global__ __launch_bounds__(256)
void attn_kernel(const float* __restrict__ bias)
{
    extern __shared__ float sm[];
    float* Qs = sm;
    float* Ks = sm + 64*QS_P;
    float* Vs = sm + 64*QS_P + 192*KS_P;
    float* Ss = Ks;

    const int tid = threadIdx.x;
    const int qt = blockIdx.x;
    const int bh = blockIdx.y;
    const int qstart = qt * 64;
    const int jbase = qstart - 128;

    const float* qg = g_q + (long)bh * S_LEN * DHEAD;
    const float* kg = g_k + (long)bh * S_LEN * DHEAD;
    const float* vg = g_v + (long)bh * S_LEN * DHEAD;

    for (int idx = tid; idx < 64*64; idx += 256)
        Qs[(idx >> 6)*QS_P + (idx & 63)] = qg[(long)(qstart + (idx >> 6))*DHEAD + (idx & 63)];
    for (int idx = tid; idx < 192*64; idx += 256) {
        int j = jbase + (idx >> 6);
        float kv = 0.f, vv = 0.f;
        if (j >= 0) {
            kv = kg[(long)j*DHEAD + (idx & 63)];
            vv = vg[(long)j*DHEAD + (idx & 63)];
        }
        Ks[(idx >> 6)*KS_P + (idx & 63)] = kv;
        Vs[idx] = vv;
    }
    __syncthreads();

    const int ty = tid >> 4, tx = tid & 15;

    {
        float acc[4][12];
        #pragma unroll
        for (int i = 0; i < 4; i++)
            #pragma unroll
            for (int j = 0; j < 12; j++) acc[i][j] = 0.f;

        #pragma unroll 4
        for (int k = 0; k < 64; k++) {
            float rq[4], rk[12];
            #pragma unroll
            for (int i = 0; i < 4; i++) rq[i] = Qs[(ty*4+i)*QS_P + k];
            #pragma unroll
            for (int j = 0; j < 12; j++) rk[j] = Ks[(tx*12+j)*KS_P + k];
            #pragma unroll
            for (int i = 0; i < 4; i++)
                #pragma unroll
                for (int j = 0; j < 12; j++)
                    acc[i][j] = fmaf(rq[i], rk[j], acc[i][j]);
        }
        __syncthreads();

        const float scale = 0.125f;
        const float* bb = bias + (long)bh * S_LEN * S_LEN;
        #pragma unroll
        for (int i = 0; i < 4; i++) {
            int gi = qstart + ty*4 + i;
            #pragma unroll
            for (int j = 0; j < 12; j++) {
                int c = tx*12 + j;
                int gj = jbase + c;
                float val = NEGBIG;
                if (gj >= 0 && gj <= gi && (gi - gj) <= 128)
                    val = acc[i][j]*scale + bb[(long)gi*S_LEN + gj];
                Ss[(ty*4+i)*192 + c] = val;
            }
        }
    }
    __syncthreads();

    {
        const int w = tid >> 5, lane = tid & 31;
        for (int rr = 0; rr < 8; rr++) {
            int r = w*8 + rr;
            float vals[6];
            float m = NEGBIG;
            #pragma unroll
            for (int t = 0; t < 6; t++) {
                vals[t] = Ss[r*192 + t*32 + lane];
                m = fmaxf(m, vals[t]);
            }
            #pragma unroll
            for (int o = 16; o > 0; o >>= 1)
                m = fmaxf(m, __shfl_xor_sync(0xffffffffu, m, o));
            float ssum = 0.f;
            #pragma unroll
            for (int t = 0; t < 6; t++) {
                vals[t] = __expf(vals[t] - m);
                ssum += vals[t];
            }
            #pragma unroll
            for (int o = 16; o > 0; o >>= 1)
                ssum += __shfl_xor_sync(0xffffffffu, ssum, o);
            float inv = 1.f / ssum;
            #pragma unroll
            for (int t = 0; t < 6; t++)
                Ss[r*192 + t*32 + lane] = vals[t] * inv;
        }
    }
    __syncthreads();

    {
        float acc[4][4];
        #pragma unroll
        for (int i = 0; i < 4; i++)
            #pragma unroll
            for (int j = 0; j < 4; j++) acc[i][j] = 0.f;

        #pragma unroll 4
        for (int k = 0; k < 192; k++) {
            float rp[4], rv[4];
            #pragma unroll
            for (int i = 0; i < 4; i++) rp[i] = Ss[(ty*4+i)*192 + k];
            #pragma unroll
            for (int j = 0; j < 4; j++) rv[j] = Vs[k*64 + tx*4 + j];
            #pragma unroll
            for (int i = 0; i < 4; i++)
                #pragma unroll
                for (int j = 0; j < 4; j++)
                    acc[i][j] = fmaf(rp[i], rv[j], acc[i][j]);
        }

        const int b = bh >> 4, h = bh & 15;
        #pragma unroll
        for (int i = 0; i < 4; i++) {
            int gi = qstart + ty*4 + i;
            #pragma unroll
            for (int j = 0; j < 4; j++) {
                g_att[((long)(b*S_LEN + gi))*D_MODEL + h*DHEAD + tx*4 + j] = acc[i][j];
            }
        }
    }
}

// ---------------------------------------------------------------------------
extern "C" void kernel_launch(void* const* d_in, const int* in_sizes, int n_in,
                              void* d_out, int out_size)
{
    const float* x    = (const float*)d_in[0];
    const float* bias = (const float*)d_in[1];
    // d_in[2] = causal mask (recomputed analytically in-kernel)
    const float* Wqkv = (const float*)d_in[3];
    const float* Wout = (const float*)d_in[4];
    float* out = (float*)d_out;

    __nv_bfloat16 *xh, *xl, *ath, *atl, *wqh, *wql, *woh, *wol;
    cudaGetSymbolAddress((void**)&xh,  g_xh);  cudaGetSymbolAddress((void**)&xl,  g_xl);
    cudaGetSymbolAddress((void**)&ath, g_ath); cudaGetSymbolAddress((void**)&atl, g_atl);
    cudaGetSymbolAddress((void**)&wqh, g_wqh); cudaGetSymbolAddress((void**)&wql, g_wql);
    cudaGetSymbolAddress((void**)&woh, g_woh); cudaGetSymbolAddress((void**)&wol, g_wol);
    float* att; cudaGetSymbolAddress((void**)&att, g_att);

    cudaFuncSetAttribute(bf16_gemm_kernel<3072, true>,
                         cudaFuncAttributeMaxDynamicSharedMemorySize, GEMM_SMEM_BYTES);
    cudaFuncSetAttribute(bf16_gemm_kernel<1024, false>,
                         cudaFuncAttributeMaxDynamicSharedMemorySize, GEMM_SMEM_BYTES);
    cudaFuncSetAttribute(attn_kernel,
                         cudaFuncAttributeMaxDynamicSharedMemorySize,
                         ATTN_SMEM_FLOATS * (int)sizeof(float));

    // Pre-passes: split x; split+transpose weights
    split_plain_kernel<<<4096, 256>>>(x, xh, xl);
    transpose_split_kernel<<<dim3(3072/32, 1024/32), dim3(32, 8)>>>(Wqkv, wqh, wql, 1024, 3072);
    transpose_split_kernel<<<dim3(1024/32, 1024/32), dim3(32, 8)>>>(Wout, woh, wol, 1024, 1024);

    // QKV projection (M=4096, N=3072)
    bf16_gemm_kernel<3072, true><<<dim3(24, 32), 256, GEMM_SMEM_BYTES>>>(
        xh, xl, wqh, wql, nullptr);

    // Banded attention
    attn_kernel<<<dim3(32, 32), 256, ATTN_SMEM_FLOATS * (int)sizeof(float)>>>(bias);

    // Split attention output, then output projection (M=4096, N=1024)
    split_plain_kernel<<<4096, 256>>>(att, ath, atl);
    bf16_gemm_kernel<1024, false><<<dim3(8, 32), 256, GEMM_SMEM_BYTES>>>(
        ath, atl, woh, wol, out);
}